// round 1
// baseline (speedup 1.0000x reference)
#include <cuda_runtime.h>
#include <math.h>

#define NUM_TOKENS 16384
#define D_MODEL    2048
#define NUM_EXP    8
#define TOK_PER_WARP 8
#define WARPS_PER_BLOCK 8
#define THREADS (WARPS_PER_BLOCK * 32)
#define TOK_PER_BLOCK (TOK_PER_WARP * WARPS_PER_BLOCK)   // 64
#define D4 (D_MODEL / 4)                                  // 512 float4 per row
#define ITERS (D4 / 32)                                   // 16 iterations per row

extern __shared__ float sW[];   // NUM_EXP * D_MODEL floats = 64 KB

__global__ __launch_bounds__(THREADS)
void gate_kernel(const float* __restrict__ x,
                 const float* __restrict__ W,
                 float* __restrict__ out,
                 int write_experts)
{
    // --- Stage W into shared memory (64 KB), float4 coalesced ---
    const float4* W4 = reinterpret_cast<const float4*>(W);
    float4* sW4 = reinterpret_cast<float4*>(sW);
    #pragma unroll
    for (int i = threadIdx.x; i < NUM_EXP * D4; i += THREADS) {
        sW4[i] = W4[i];
    }
    __syncthreads();

    const int warp = threadIdx.x >> 5;
    const int lane = threadIdx.x & 31;
    const int tok0 = blockIdx.x * TOK_PER_BLOCK + warp * TOK_PER_WARP;

    float acc[NUM_EXP][TOK_PER_WARP];
    #pragma unroll
    for (int e = 0; e < NUM_EXP; e++)
        #pragma unroll
        for (int t = 0; t < TOK_PER_WARP; t++)
            acc[e][t] = 0.0f;

    const float4* x4 = reinterpret_cast<const float4*>(x);

    // --- Main loop: each warp computes 8 tokens x 8 experts dot products ---
    #pragma unroll 1
    for (int it = 0; it < ITERS; it++) {
        const int col = it * 32 + lane;   // float4 column within the row

        float4 xv[TOK_PER_WARP];
        #pragma unroll
        for (int t = 0; t < TOK_PER_WARP; t++)
            xv[t] = x4[(size_t)(tok0 + t) * D4 + col];

        #pragma unroll
        for (int e = 0; e < NUM_EXP; e++) {
            float4 wv = sW4[e * D4 + col];
            #pragma unroll
            for (int t = 0; t < TOK_PER_WARP; t++) {
                float a = acc[e][t];
                a = fmaf(xv[t].x, wv.x, a);
                a = fmaf(xv[t].y, wv.y, a);
                a = fmaf(xv[t].z, wv.z, a);
                a = fmaf(xv[t].w, wv.w, a);
                acc[e][t] = a;
            }
        }
    }

    // --- Warp butterfly reduction: every lane ends with the full 8x8 sums ---
    #pragma unroll
    for (int off = 16; off >= 1; off >>= 1) {
        #pragma unroll
        for (int e = 0; e < NUM_EXP; e++)
            #pragma unroll
            for (int t = 0; t < TOK_PER_WARP; t++)
                acc[e][t] += __shfl_xor_sync(0xFFFFFFFFu, acc[e][t], off);
    }

    // Lane l picks token l's logits via compile-time select chain (no spills)
    float logit[NUM_EXP];
    #pragma unroll
    for (int e = 0; e < NUM_EXP; e++) {
        float v = acc[e][0];
        #pragma unroll
        for (int t = 1; t < TOK_PER_WARP; t++)
            v = (lane == t) ? acc[e][t] : v;
        logit[e] = v;
    }

    if (lane < TOK_PER_WARP) {
        const int tok = tok0 + lane;

        // top-2 scan; strict '>' keeps the lowest index on ties (JAX top_k order)
        float v1 = logit[0], v2 = -INFINITY;
        int   i1 = 0,        i2 = 0;
        #pragma unroll
        for (int e = 1; e < NUM_EXP; e++) {
            float le = logit[e];
            if (le > v1)      { v2 = v1; i2 = i1; v1 = le; i1 = e; }
            else if (le > v2) { v2 = le; i2 = e; }
        }

        // softmax + top-2 + renormalize collapses to a 2-way softmax
        float r  = __expf(v2 - v1);
        float w1 = 1.0f / (1.0f + r);
        float w2 = 1.0f - w1;

        out[tok * 2 + 0] = w1;
        out[tok * 2 + 1] = w2;
        if (write_experts) {
            out[2 * NUM_TOKENS + tok * 2 + 0] = (float)i1;
            out[2 * NUM_TOKENS + tok * 2 + 1] = (float)i2;
        }
    }
}

extern "C" void kernel_launch(void* const* d_in, const int* in_sizes, int n_in,
                              void* d_out, int out_size)
{
    const float* x = (const float*)d_in[0];
    const float* W = (const float*)d_in[1];
    float* out = (float*)d_out;

    // Output layout: [routing_weights (T*2 floats)] then optionally
    // [selected_experts as float (T*2)] if the harness buffer has room.
    int write_experts = (out_size >= 4 * NUM_TOKENS) ? 1 : 0;

    const int smem = NUM_EXP * D_MODEL * (int)sizeof(float);  // 65536
    cudaFuncSetAttribute(gate_kernel, cudaFuncAttributeMaxDynamicSharedMemorySize, smem);

    gate_kernel<<<NUM_TOKENS / TOK_PER_BLOCK, THREADS, smem>>>(x, W, out, write_experts);
}